// round 13
// baseline (speedup 1.0000x reference)
#include <cuda_runtime.h>
#include <cuda_fp16.h>
#include <cstdint>

#define NROWS 20736
#define DIMX 1024
#define HIDX 4096
#define KIN  3072

// ---------------- scratch (device globals; no allocs) ----------------
__device__ __align__(16) __half g_A0[(size_t)NROWS * KIN];
__device__ __align__(16) __half g_hx[(size_t)NROWS * DIMX];
__device__ __align__(16) __half g_ux[(size_t)NROWS * HIDX];
__device__ __align__(16) float  g_h [(size_t)NROWS * DIMX];

__device__ __align__(16) __half g_wq_in[DIMX * KIN];
__device__ __align__(16) __half g_wq1[2 * HIDX * DIMX];
__device__ __align__(16) __half g_wq2[2 * DIMX * HIDX];
__device__ __align__(16) __half g_wqz[DIMX * DIMX];
__device__ __align__(16) __half g_wqm[DIMX];

#define NPART 512
__device__ double g_part[8][NPART];
__device__ float  g_scale[8];
__device__ int    g_tick[8];

// ---------------- merged prep: abssum (t<7) + concat->fp16 (t==7) ----------------
struct P7 { const float* w[7]; long n[7]; };
struct Q7 { const float* w[7]; __half* q[7]; long n[7]; };

__global__ void k_absbuild(P7 p, const float4* __restrict__ x,
                           const float4* __restrict__ y, const float4* __restrict__ s) {
    int t = blockIdx.y;
    if (t == 7) {
        int j = threadIdx.x;
        for (int row = blockIdx.x; row < NROWS; row += NPART) {
            size_t ib = (size_t)row * 256 + j;
            float4 vx = x[ib], vy = y[ib], vz = s[ib];
            __half2* dst = (__half2*)(g_A0 + (size_t)row * KIN);
            dst[j * 2 + 0]        = __floats2half2_rn(vx.x, vx.y);
            dst[j * 2 + 1]        = __floats2half2_rn(vx.z, vx.w);
            dst[512 + j * 2 + 0]  = __floats2half2_rn(vy.x, vy.y);
            dst[512 + j * 2 + 1]  = __floats2half2_rn(vy.z, vy.w);
            dst[1024 + j * 2 + 0] = __floats2half2_rn(vz.x, vz.y);
            dst[1024 + j * 2 + 1] = __floats2half2_rn(vz.z, vz.w);
        }
        return;
    }
    const float4* __restrict__ w = (const float4*)p.w[t];
    long n4 = p.n[t] >> 2;
    double sum = 0.0;
    for (long i = (long)blockIdx.x * blockDim.x + threadIdx.x; i < n4;
         i += (long)NPART * blockDim.x) {
        float4 v = w[i];
        sum += fabs((double)v.x); sum += fabs((double)v.y);
        sum += fabs((double)v.z); sum += fabs((double)v.w);
    }
    __shared__ double sh[256];
    sh[threadIdx.x] = sum;
    __syncthreads();
    for (int o = 128; o > 0; o >>= 1) {
        if (threadIdx.x < o) sh[threadIdx.x] += sh[threadIdx.x + o];
        __syncthreads();
    }
    if (threadIdx.x == 0) g_part[t][blockIdx.x] = sh[0];
}

__global__ void k_finalize() {
    int i = threadIdx.x;
    if (i < 8) g_tick[i] = 0;
    if (i >= 7) return;
    const double cnt[7] = {3145728.0, 4194304.0, 4194304.0, 4194304.0,
                           4194304.0, 1048576.0, 1024.0};
    double s = 0.0;
    for (int j = 0; j < NPART; j++) s += g_part[i][j];
    g_scale[i] = (float)(s / cnt[i]) + 1e-8f;
}

__global__ void k_quant7(Q7 p) {
    int t = blockIdx.y;
    const float4* __restrict__ w = (const float4*)p.w[t];
    __half* __restrict__ q = p.q[t];
    long n4 = p.n[t] >> 2;
    float a = g_scale[t];
    for (long i = (long)blockIdx.x * blockDim.x + threadIdx.x; i < n4;
         i += (long)gridDim.x * blockDim.x) {
        float4 v = w[i];
        float q0 = fminf(1.0f, fmaxf(-1.0f, rintf(v.x / a)));
        float q1 = fminf(1.0f, fmaxf(-1.0f, rintf(v.y / a)));
        float q2 = fminf(1.0f, fmaxf(-1.0f, rintf(v.z / a)));
        float q3 = fminf(1.0f, fmaxf(-1.0f, rintf(v.w / a)));
        __half2* d = (__half2*)(q + i * 4);
        d[0] = __floats2half2_rn(q0, q1);
        d[1] = __floats2half2_rn(q2, q3);
    }
}

// ---------------- GEMM: persistent, 128x128, K-chunk 64, fp16-acc chunks ----------------
__device__ __forceinline__ void cpasync16(uint32_t smem, const void* gmem) {
    asm volatile("cp.async.cg.shared.global [%0], [%1], 16;\n" ::"r"(smem), "l"(gmem));
}
__device__ __forceinline__ uint32_t smem_u32(const void* p) {
    uint32_t a;
    asm("{ .reg .u64 t; cvta.to.shared.u64 t, %1; cvt.u32.u64 %0, t; }" : "=r"(a) : "l"(p));
    return a;
}
__device__ __forceinline__ float gelu_f(float x) {
    return 0.5f * x * (1.0f + erff(x * 0.70710678118654752f));
}

enum { EPI_H = 0, EPI_GELU = 1, EPI_RES = 2, EPI_Z = 3 };

#define STG 36864            // A 128x144B + B 128x144B
#define SMEM_DYN (3 * STG)
#define NPCTA 296

#define LDSM4(d0, d1, d2, d3, a) \
    asm volatile("ldmatrix.sync.aligned.m8n8.x4.shared.b16 {%0,%1,%2,%3}, [%4];" \
        : "=r"(d0), "=r"(d1), "=r"(d2), "=r"(d3) : "r"(a))

template <int K>
__device__ __forceinline__ void ld_stage(uint32_t sb, const __half* __restrict__ A,
                                         const __half* __restrict__ Bw,
                                         int bm, int bn, int k0, int tid) {
#pragma unroll
    for (int i = 0; i < 4; i++) {
        int j = tid + i * 256;
        int r = j >> 3, c = (j & 7) * 16;
        cpasync16(sb + r * 144 + c, A + (size_t)(bm + r) * K + k0 + (c >> 1));
    }
#pragma unroll
    for (int i = 0; i < 4; i++) {
        int j = tid + i * 256;
        int r = j >> 3, c = (j & 7) * 16;
        cpasync16(sb + 18432 + r * 144 + c, Bw + (size_t)(bn + r) * K + k0 + (c >> 1));
    }
}

#define LDFRAGS(pb, aB, bB, koff) do {                                          \
    _Pragma("unroll") for (int mf = 0; mf < 4; mf++)                            \
        LDSM4(af[pb][mf][0], af[pb][mf][1], af[pb][mf][2], af[pb][mf][3],       \
              (aB) + mf * 2304 + (koff));                                       \
    _Pragma("unroll") for (int nh = 0; nh < 2; nh++) {                          \
        uint32_t r0, r1, r2, r3;                                                \
        LDSM4(r0, r1, r2, r3, (bB) + nh * 2304 + (koff));                       \
        bf[pb][nh * 2 + 0][0] = r0; bf[pb][nh * 2 + 0][1] = r2;                 \
        bf[pb][nh * 2 + 1][0] = r1; bf[pb][nh * 2 + 1][1] = r3;                 \
    }                                                                           \
} while (0)

// two chained fp16-acc MMAs (K=32) then promote into fp32 master acc
#define MMA16H(c0, c1, a, b) \
    asm volatile("mma.sync.aligned.m16n8k16.row.col.f16.f16.f16.f16 "           \
                 "{%0,%1},{%2,%3,%4,%5},{%6,%7},{%0,%1};"                       \
                 : "+r"(c0), "+r"(c1)                                           \
                 : "r"((a)[0]), "r"((a)[1]), "r"((a)[2]), "r"((a)[3]),          \
                   "r"((b)[0]), "r"((b)[1]))

#define DOMMAS_PAIR() do {                                                      \
    _Pragma("unroll") for (int mf = 0; mf < 4; mf++)                            \
        _Pragma("unroll") for (int nf = 0; nf < 4; nf++) {                      \
            uint32_t c0 = 0u, c1 = 0u;                                          \
            MMA16H(c0, c1, af[0][mf], bf[0][nf]);                               \
            MMA16H(c0, c1, af[1][mf], bf[1][nf]);                               \
            float2 f0 = __half22float2(*(__half2*)&c0);                         \
            float2 f1 = __half22float2(*(__half2*)&c1);                         \
            acc[mf][nf][0] += f0.x; acc[mf][nf][1] += f0.y;                     \
            acc[mf][nf][2] += f1.x; acc[mf][nf][3] += f1.y;                     \
        }                                                                       \
} while (0)

template <int EPI, int K>
__global__ void __launch_bounds__(256, 2)
k_gemm(const __half* __restrict__ A, const __half* __restrict__ Bw,
       const float* __restrict__ bias, int sidx, int Ncols, int nbx, int ntiles,
       int slot, float* __restrict__ Hio, __half* __restrict__ Oh,
       float* __restrict__ Zout) {
    extern __shared__ char dsm[];
    __shared__ int s_tile;
    const uint32_t base = smem_u32(dsm);
    const int tid = threadIdx.x, lane = tid & 31, wid = tid >> 5;
    const int wm = (wid >> 2) * 64, wn = (wid & 3) * 32;
    const int KT = K / 64;
    const float a_s = g_scale[sidx];
    const uint32_t aOff = (wm + (lane & 15)) * 144 + ((lane >> 4) << 4);
    const uint32_t bOff = 18432 + (wn + (lane & 15)) * 144 + ((lane >> 4) << 4);

    if (tid == 0) s_tile = atomicAdd(&g_tick[slot], 1);
    __syncthreads();
    int t = s_tile;
    if (t >= ntiles) return;

    int sl = 0;
    {
        int bm = (t / nbx) * 128, bn = (t % nbx) * 128;
        ld_stage<K>(base, A, Bw, bm, bn, 0, tid);
        asm volatile("cp.async.commit_group;\n");
        ld_stage<K>(base + STG, A, Bw, bm, bn, 64, tid);
        asm volatile("cp.async.commit_group;\n");
    }

    for (;;) {
        const int bm = (t / nbx) * 128, bn = (t % nbx) * 128;

        float acc[4][4][4];
#pragma unroll
        for (int i = 0; i < 4; i++)
#pragma unroll
            for (int j = 0; j < 4; j++)
#pragma unroll
                for (int k = 0; k < 4; k++) acc[i][j][k] = 0.0f;

        for (int kt = 0; kt < KT; kt++) {
            asm volatile("cp.async.wait_group 1;\n" ::: "memory");
            __syncthreads();

            const int ls = (sl + 2) % 3;
            if (kt == KT - 3) {
                if (tid == 0) s_tile = atomicAdd(&g_tick[slot], 1);
                ld_stage<K>(base + ls * STG, A, Bw, bm, bn, (kt + 2) * 64, tid);
            } else if (kt + 2 < KT) {
                ld_stage<K>(base + ls * STG, A, Bw, bm, bn, (kt + 2) * 64, tid);
            } else {
                int nt = s_tile;
                if (nt < ntiles)
                    ld_stage<K>(base + ls * STG, A, Bw, (nt / nbx) * 128,
                                (nt % nbx) * 128, (kt + 2 - KT) * 64, tid);
            }
            asm volatile("cp.async.commit_group;\n");

            const uint32_t sb = base + sl * STG;
            const uint32_t aB = sb + aOff, bB = sb + bOff;
            uint32_t af[2][4][4], bf[2][4][2];
#pragma unroll
            for (int ksp = 0; ksp < 2; ksp++) {
                LDFRAGS(0, aB, bB, (2 * ksp + 0) * 32);
                LDFRAGS(1, aB, bB, (2 * ksp + 1) * 32);
                DOMMAS_PAIR();        // K=32 in fp16 acc, promoted to fp32
            }
            sl = (sl + 1) % 3;
        }

        const int nt = s_tile;

#pragma unroll
        for (int mf = 0; mf < 4; mf++) {
#pragma unroll
            for (int nf = 0; nf < 4; nf++) {
                int col = bn + wn + nf * 8 + (lane & 3) * 2;
                float b0 = bias[col], b1 = bias[col + 1];
#pragma unroll
                for (int h2 = 0; h2 < 2; h2++) {
                    int row = bm + wm + mf * 16 + (lane >> 2) + h2 * 8;
                    size_t o = (size_t)row * Ncols + col;
                    float v0 = fmaf(a_s, acc[mf][nf][h2 * 2 + 0], b0);
                    float v1 = fmaf(a_s, acc[mf][nf][h2 * 2 + 1], b1);
                    if (EPI == EPI_RES) {
                        float2 hp = *(const float2*)&Hio[o];
                        v0 += hp.x; v1 += hp.y;
                    }
                    if (EPI == EPI_GELU) { v0 = gelu_f(v0); v1 = gelu_f(v1); }
                    if (EPI == EPI_H || EPI == EPI_RES) {
                        float2 w; w.x = v0; w.y = v1;
                        *(float2*)&Hio[o] = w;
                    }
                    if (EPI == EPI_Z) {
                        float2 w; w.x = v0; w.y = v1;
                        *(float2*)&Zout[o] = w;
                    } else {
                        __half2 ph;
                        ph.x = __float2half_rn(v0);
                        ph.y = __float2half_rn(v1);
                        *(__half2*)&Oh[o] = ph;
                    }
                }
            }
        }

        if (nt >= ntiles) break;
        t = nt;
    }
}

// ---------------- focus mask ----------------
__global__ void k_focus(const float* __restrict__ h, const float* __restrict__ bm,
                        float* __restrict__ out) {
    int row = blockIdx.x * 8 + (threadIdx.x >> 5);
    int lane = threadIdx.x & 31;
    if (row >= NROWS) return;
    const float* hr = h + (size_t)row * DIMX;
    float sum = 0.0f;
    for (int c = lane; c < DIMX; c += 32) sum += hr[c] * __half2float(g_wqm[c]);
#pragma unroll
    for (int o = 16; o; o >>= 1) sum += __shfl_xor_sync(0xffffffffu, sum, o);
    if (lane == 0) {
        float v = g_scale[6] * sum + bm[0];
        out[row] = 1.0f / (1.0f + expf(-v));
    }
}

// ---------------- launcher ----------------
extern "C" void kernel_launch(void* const* d_in, const int* in_sizes, int n_in,
                              void* d_out, int out_size) {
    const float* x    = (const float*)d_in[0];
    const float* y    = (const float*)d_in[1];
    const float* sp   = (const float*)d_in[2];
    const float* W_in = (const float*)d_in[3];
    const float* b_in = (const float*)d_in[4];
    const float* W1   = (const float*)d_in[5];
    const float* b1   = (const float*)d_in[6];
    const float* W2   = (const float*)d_in[7];
    const float* b2   = (const float*)d_in[8];
    const float* W_z  = (const float*)d_in[9];
    const float* b_z  = (const float*)d_in[10];
    const float* W_m  = (const float*)d_in[11];
    const float* b_m  = (const float*)d_in[12];
    float* out = (float*)d_out;

    void *pA0, *phx, *pux, *ph, *pwin, *pw1, *pw2, *pwz, *pwm;
    cudaGetSymbolAddress(&pA0, g_A0);
    cudaGetSymbolAddress(&phx, g_hx);
    cudaGetSymbolAddress(&pux, g_ux);
    cudaGetSymbolAddress(&ph, g_h);
    cudaGetSymbolAddress(&pwin, g_wq_in);
    cudaGetSymbolAddress(&pw1, g_wq1);
    cudaGetSymbolAddress(&pw2, g_wq2);
    cudaGetSymbolAddress(&pwz, g_wqz);
    cudaGetSymbolAddress(&pwm, g_wqm);

    __half* wq_in = (__half*)pwin;
    __half* wq1   = (__half*)pw1;
    __half* wq2   = (__half*)pw2;

    cudaFuncSetAttribute((const void*)k_gemm<EPI_H, KIN>,
                         cudaFuncAttributeMaxDynamicSharedMemorySize, SMEM_DYN);
    cudaFuncSetAttribute((const void*)k_gemm<EPI_GELU, DIMX>,
                         cudaFuncAttributeMaxDynamicSharedMemorySize, SMEM_DYN);
    cudaFuncSetAttribute((const void*)k_gemm<EPI_RES, HIDX>,
                         cudaFuncAttributeMaxDynamicSharedMemorySize, SMEM_DYN);
    cudaFuncSetAttribute((const void*)k_gemm<EPI_Z, DIMX>,
                         cudaFuncAttributeMaxDynamicSharedMemorySize, SMEM_DYN);

    P7 pa;
    pa.w[0] = W_in;                      pa.n[0] = (long)DIMX * KIN;
    pa.w[1] = W1;                        pa.n[1] = (long)HIDX * DIMX;
    pa.w[2] = W1 + (size_t)HIDX * DIMX;  pa.n[2] = (long)HIDX * DIMX;
    pa.w[3] = W2;                        pa.n[3] = (long)DIMX * HIDX;
    pa.w[4] = W2 + (size_t)DIMX * HIDX;  pa.n[4] = (long)DIMX * HIDX;
    pa.w[5] = W_z;                       pa.n[5] = (long)DIMX * DIMX;
    pa.w[6] = W_m;                       pa.n[6] = (long)DIMX;
    k_absbuild<<<dim3(NPART, 8), 256>>>(pa, (const float4*)x, (const float4*)y,
                                        (const float4*)sp);
    k_finalize<<<1, 32>>>();

    Q7 qa;
    for (int i = 0; i < 7; i++) { qa.w[i] = pa.w[i]; qa.n[i] = pa.n[i]; }
    qa.q[0] = wq_in;
    qa.q[1] = wq1;
    qa.q[2] = wq1 + (size_t)HIDX * DIMX;
    qa.q[3] = wq2;
    qa.q[4] = wq2 + (size_t)DIMX * HIDX;
    qa.q[5] = (__half*)pwz;
    qa.q[6] = (__half*)pwm;
    k_quant7<<<dim3(2048, 7), 256>>>(qa);

    const int TM = NROWS / 128;  // 162

    // launch 4 (ncu-captured): h = A0 @ Wq_in^T + b_in
    k_gemm<EPI_H, KIN><<<NPCTA, 256, SMEM_DYN>>>(
        (__half*)pA0, wq_in, b_in, 0, DIMX, 8, TM * 8, 0,
        (float*)ph, (__half*)phx, nullptr);
    for (int l = 0; l < 2; l++) {
        k_gemm<EPI_GELU, DIMX><<<NPCTA, 256, SMEM_DYN>>>(
            (__half*)phx, wq1 + (size_t)l * HIDX * DIMX, b1 + (size_t)l * HIDX,
            1 + l, HIDX, 32, TM * 32, 1 + 2 * l, nullptr, (__half*)pux, nullptr);
        k_gemm<EPI_RES, HIDX><<<NPCTA, 256, SMEM_DYN>>>(
            (__half*)pux, wq2 + (size_t)l * DIMX * HIDX, b2 + (size_t)l * DIMX,
            3 + l, DIMX, 8, TM * 8, 2 + 2 * l, (float*)ph, (__half*)phx, nullptr);
    }
    k_gemm<EPI_Z, DIMX><<<NPCTA, 256, SMEM_DYN>>>(
        (__half*)phx, (__half*)pwz, b_z, 5, DIMX, 8, TM * 8, 5,
        nullptr, nullptr, out);
    k_focus<<<NROWS / 8, 256>>>((const float*)ph, b_m, out + (size_t)NROWS * DIMX);
}

// round 14
// speedup vs baseline: 1.2524x; 1.2524x over previous
#include <cuda_runtime.h>
#include <cuda_fp16.h>
#include <cstdint>

#define NROWS 20736
#define DIMX 1024
#define HIDX 4096
#define KIN  3072
#define TM   162            // row blocks of 128

// ---------------- scratch (device globals; no allocs) ----------------
__device__ __align__(16) __half g_A0[(size_t)NROWS * KIN];
__device__ __align__(16) __half g_hx[(size_t)NROWS * DIMX];
__device__ __align__(16) __half g_ux[(size_t)NROWS * HIDX];
__device__ __align__(16) float  g_h [(size_t)NROWS * DIMX];

__device__ __align__(16) __half g_wq_in[DIMX * KIN];
__device__ __align__(16) __half g_wq1[2 * HIDX * DIMX];
__device__ __align__(16) __half g_wq2[2 * DIMX * HIDX];
__device__ __align__(16) __half g_wqz[DIMX * DIMX];
__device__ __align__(16) __half g_wqm[DIMX];

#define NPART 512
__device__ double g_part[8][NPART];
__device__ float  g_scale[8];
__device__ int    g_tick[8];
__device__ int    g_done[5][TM];

// ---------------- merged prep: abssum (t<7) + concat->fp16 (t==7) ----------------
struct P7 { const float* w[7]; long n[7]; };
struct Q7 { const float* w[7]; __half* q[7]; long n[7]; };

__global__ void k_absbuild(P7 p, const float4* __restrict__ x,
                           const float4* __restrict__ y, const float4* __restrict__ s) {
    int t = blockIdx.y;
    if (t == 7) {
        int j = threadIdx.x;
        for (int row = blockIdx.x; row < NROWS; row += NPART) {
            size_t ib = (size_t)row * 256 + j;
            float4 vx = x[ib], vy = y[ib], vz = s[ib];
            __half2* dst = (__half2*)(g_A0 + (size_t)row * KIN);
            dst[j * 2 + 0]        = __floats2half2_rn(vx.x, vx.y);
            dst[j * 2 + 1]        = __floats2half2_rn(vx.z, vx.w);
            dst[512 + j * 2 + 0]  = __floats2half2_rn(vy.x, vy.y);
            dst[512 + j * 2 + 1]  = __floats2half2_rn(vy.z, vy.w);
            dst[1024 + j * 2 + 0] = __floats2half2_rn(vz.x, vz.y);
            dst[1024 + j * 2 + 1] = __floats2half2_rn(vz.z, vz.w);
        }
        return;
    }
    const float4* __restrict__ w = (const float4*)p.w[t];
    long n4 = p.n[t] >> 2;
    double sum = 0.0;
    for (long i = (long)blockIdx.x * blockDim.x + threadIdx.x; i < n4;
         i += (long)NPART * blockDim.x) {
        float4 v = w[i];
        sum += fabs((double)v.x); sum += fabs((double)v.y);
        sum += fabs((double)v.z); sum += fabs((double)v.w);
    }
    __shared__ double sh[256];
    sh[threadIdx.x] = sum;
    __syncthreads();
    for (int o = 128; o > 0; o >>= 1) {
        if (threadIdx.x < o) sh[threadIdx.x] += sh[threadIdx.x + o];
        __syncthreads();
    }
    if (threadIdx.x == 0) g_part[t][blockIdx.x] = sh[0];
}

__global__ void k_finalize() {
    int i = threadIdx.x;   // 1024 threads
    if (i < 8) g_tick[i] = 0;
    for (int j = i; j < 5 * TM; j += 1024) ((int*)g_done)[j] = 0;
    if (i >= 7) return;
    const double cnt[7] = {3145728.0, 4194304.0, 4194304.0, 4194304.0,
                           4194304.0, 1048576.0, 1024.0};
    double s = 0.0;
    for (int j = 0; j < NPART; j++) s += g_part[i][j];
    g_scale[i] = (float)(s / cnt[i]) + 1e-8f;
}

__global__ void k_quant7(Q7 p) {
    int t = blockIdx.y;
    const float4* __restrict__ w = (const float4*)p.w[t];
    __half* __restrict__ q = p.q[t];
    long n4 = p.n[t] >> 2;
    float a = g_scale[t];
    for (long i = (long)blockIdx.x * blockDim.x + threadIdx.x; i < n4;
         i += (long)gridDim.x * blockDim.x) {
        float4 v = w[i];
        float q0 = fminf(1.0f, fmaxf(-1.0f, rintf(v.x / a)));
        float q1 = fminf(1.0f, fmaxf(-1.0f, rintf(v.y / a)));
        float q2 = fminf(1.0f, fmaxf(-1.0f, rintf(v.z / a)));
        float q3 = fminf(1.0f, fmaxf(-1.0f, rintf(v.w / a)));
        __half2* d = (__half2*)(q + i * 4);
        d[0] = __floats2half2_rn(q0, q1);
        d[1] = __floats2half2_rn(q2, q3);
    }
}

// ---------------- fused persistent GEMM chain + focus ----------------
__device__ __forceinline__ void cpasync16(uint32_t smem, const void* gmem) {
    asm volatile("cp.async.cg.shared.global [%0], [%1], 16;\n" ::"r"(smem), "l"(gmem));
}
__device__ __forceinline__ uint32_t smem_u32(const void* p) {
    uint32_t a;
    asm("{ .reg .u64 t; cvta.to.shared.u64 t, %1; cvt.u32.u64 %0, t; }" : "=r"(a) : "l"(p));
    return a;
}
__device__ __forceinline__ float gelu_f(float x) {
    return 0.5f * x * (1.0f + erff(x * 0.70710678118654752f));
}
__device__ __forceinline__ void nsleep(unsigned t) {
    asm volatile("nanosleep.u32 %0;" ::"r"(t));
}

enum { EPI_H = 0, EPI_GELU = 1, EPI_RES = 2, EPI_Z = 3 };

#define STG 36864            // A 128x144B + B 128x144B
#define SMEM_DYN (3 * STG)
#define NPCTA 296

#define LDSM4(d0, d1, d2, d3, a) \
    asm volatile("ldmatrix.sync.aligned.m8n8.x4.shared.b16 {%0,%1,%2,%3}, [%4];" \
        : "=r"(d0), "=r"(d1), "=r"(d2), "=r"(d3) : "r"(a))

__device__ __forceinline__ void ld_stage(uint32_t sb, const __half* __restrict__ A,
                                         const __half* __restrict__ Bw, int K,
                                         int bm, int bn, int k0, int tid) {
#pragma unroll
    for (int i = 0; i < 4; i++) {
        int j = tid + i * 256;
        int r = j >> 3, c = (j & 7) * 16;
        cpasync16(sb + r * 144 + c, A + (size_t)(bm + r) * K + k0 + (c >> 1));
    }
#pragma unroll
    for (int i = 0; i < 4; i++) {
        int j = tid + i * 256;
        int r = j >> 3, c = (j & 7) * 16;
        cpasync16(sb + 18432 + r * 144 + c, Bw + (size_t)(bn + r) * K + k0 + (c >> 1));
    }
}

struct GP {
    const __half* A; const __half* B; const float* bias;
    float* Hio; __half* Oh; float* Zout;
    int K, Ncols, nbx, ntiles, sidx, epi, depNeed;
};
struct Params { GP gp[6]; const float* bm; float* outF; };

__global__ void __launch_bounds__(256, 2)
k_fused(Params P) {
    extern __shared__ char dsm[];
    __shared__ int s_tile;
    const uint32_t base = smem_u32(dsm);
    const int tid = threadIdx.x, lane = tid & 31, wid = tid >> 5;
    const int wm = (wid >> 2) * 64, wn = (wid & 3) * 32;
    const uint32_t aOff = (wm + (lane & 15)) * 144 + ((lane >> 4) << 4);
    const uint32_t bOff = 18432 + (wn + (lane & 15)) * 144 + ((lane >> 4) << 4);

#pragma unroll 1
    for (int s = 0; s < 6; s++) {
        const GP gp = P.gp[s];
        const float a_s = g_scale[gp.sidx];
        const int KT = gp.K / 64;
        for (;;) {
            if (tid == 0) s_tile = atomicAdd(&g_tick[s], 1);
            __syncthreads();                       // rendezvous: buffers free + s_tile visible
            const int t = s_tile;
            if (t >= gp.ntiles) break;
            const int r = t / gp.nbx;
            const int bm = r * 128, bn = (t % gp.nbx) * 128;

            if (gp.depNeed) {
                if (tid == 0)
                    while (atomicAdd(&g_done[s - 1][r], 0) < gp.depNeed) nsleep(64);
                __syncthreads();
            }

            float acc[4][4][4];
#pragma unroll
            for (int i = 0; i < 4; i++)
#pragma unroll
                for (int j = 0; j < 4; j++)
#pragma unroll
                    for (int k = 0; k < 4; k++) acc[i][j][k] = 0.0f;

            ld_stage(base, gp.A, gp.B, gp.K, bm, bn, 0, tid);
            asm volatile("cp.async.commit_group;\n");
            ld_stage(base + STG, gp.A, gp.B, gp.K, bm, bn, 64, tid);
            asm volatile("cp.async.commit_group;\n");

#pragma unroll 1
            for (int kt = 0; kt < KT; kt++) {
                asm volatile("cp.async.wait_group 1;\n" ::: "memory");
                __syncthreads();
                if (kt + 2 < KT)
                    ld_stage(base + ((kt + 2) % 3) * STG, gp.A, gp.B, gp.K,
                             bm, bn, (kt + 2) * 64, tid);
                asm volatile("cp.async.commit_group;\n");

                const uint32_t sb = base + (kt % 3) * STG;
                const uint32_t aB = sb + aOff, bB = sb + bOff;
#pragma unroll
                for (int ks = 0; ks < 4; ks++) {
                    const uint32_t koff = ks * 32;
                    uint32_t af[4][4], bf[4][2];
#pragma unroll
                    for (int mf = 0; mf < 4; mf++)
                        LDSM4(af[mf][0], af[mf][1], af[mf][2], af[mf][3],
                              aB + mf * 2304 + koff);
#pragma unroll
                    for (int nh = 0; nh < 2; nh++) {
                        uint32_t r0, r1, r2, r3;
                        LDSM4(r0, r1, r2, r3, bB + nh * 2304 + koff);
                        bf[nh * 2 + 0][0] = r0; bf[nh * 2 + 0][1] = r2;
                        bf[nh * 2 + 1][0] = r1; bf[nh * 2 + 1][1] = r3;
                    }
#pragma unroll
                    for (int mf = 0; mf < 4; mf++)
#pragma unroll
                        for (int nf = 0; nf < 4; nf++)
                            asm volatile(
                                "mma.sync.aligned.m16n8k16.row.col.f32.f16.f16.f32 "
                                "{%0,%1,%2,%3},{%4,%5,%6,%7},{%8,%9},{%0,%1,%2,%3};"
                                : "+f"(acc[mf][nf][0]), "+f"(acc[mf][nf][1]),
                                  "+f"(acc[mf][nf][2]), "+f"(acc[mf][nf][3])
                                : "r"(af[mf][0]), "r"(af[mf][1]), "r"(af[mf][2]),
                                  "r"(af[mf][3]), "r"(bf[nf][0]), "r"(bf[nf][1]));
                }
            }

            const int epi = gp.epi;
#pragma unroll
            for (int mf = 0; mf < 4; mf++) {
#pragma unroll
                for (int nf = 0; nf < 4; nf++) {
                    int col = bn + wn + nf * 8 + (lane & 3) * 2;
                    float b0 = gp.bias[col], b1 = gp.bias[col + 1];
#pragma unroll
                    for (int h2 = 0; h2 < 2; h2++) {
                        int row = bm + wm + mf * 16 + (lane >> 2) + h2 * 8;
                        size_t o = (size_t)row * gp.Ncols + col;
                        float v0 = fmaf(a_s, acc[mf][nf][h2 * 2 + 0], b0);
                        float v1 = fmaf(a_s, acc[mf][nf][h2 * 2 + 1], b1);
                        if (epi == EPI_RES) {
                            float2 hp = *(const float2*)&gp.Hio[o];
                            v0 += hp.x; v1 += hp.y;
                        }
                        if (epi == EPI_GELU) { v0 = gelu_f(v0); v1 = gelu_f(v1); }
                        if (epi == EPI_H || epi == EPI_RES) {
                            float2 w; w.x = v0; w.y = v1;
                            *(float2*)&gp.Hio[o] = w;
                        }
                        if (epi == EPI_Z) {
                            float2 w; w.x = v0; w.y = v1;
                            *(float2*)&gp.Zout[o] = w;
                        } else {
                            __half2 ph;
                            ph.x = __float2half_rn(v0);
                            ph.y = __float2half_rn(v1);
                            *(__half2*)&gp.Oh[o] = ph;
                        }
                    }
                }
            }

            __threadfence();
            __syncthreads();
            if (tid == 0 && s < 5) atomicAdd(&g_done[s][r], 1);
        }
    }

    // ---- focus stage: rowblock tiles, dep on done[4][r]==8 ----
    for (;;) {
        if (tid == 0) s_tile = atomicAdd(&g_tick[6], 1);
        __syncthreads();
        const int r = s_tile;
        if (r >= TM) break;
        if (tid == 0)
            while (atomicAdd(&g_done[4][r], 0) < 8) nsleep(64);
        __syncthreads();
        const float bmv = P.bm[0];
#pragma unroll 1
        for (int i = 0; i < 16; i++) {
            int row = r * 128 + wid * 16 + i;
            const float* hr = g_h + (size_t)row * DIMX;
            float sum = 0.0f;
            for (int c = lane; c < DIMX; c += 32)
                sum += hr[c] * __half2float(g_wqm[c]);
#pragma unroll
            for (int o = 16; o; o >>= 1) sum += __shfl_xor_sync(0xffffffffu, sum, o);
            if (lane == 0) {
                float v = g_scale[6] * sum + bmv;
                P.outF[row] = 1.0f / (1.0f + expf(-v));
            }
        }
    }
}

// ---------------- launcher ----------------
extern "C" void kernel_launch(void* const* d_in, const int* in_sizes, int n_in,
                              void* d_out, int out_size) {
    const float* x    = (const float*)d_in[0];
    const float* y    = (const float*)d_in[1];
    const float* sp   = (const float*)d_in[2];
    const float* W_in = (const float*)d_in[3];
    const float* b_in = (const float*)d_in[4];
    const float* W1   = (const float*)d_in[5];
    const float* b1   = (const float*)d_in[6];
    const float* W2   = (const float*)d_in[7];
    const float* b2   = (const float*)d_in[8];
    const float* W_z  = (const float*)d_in[9];
    const float* b_z  = (const float*)d_in[10];
    const float* W_m  = (const float*)d_in[11];
    const float* b_m  = (const float*)d_in[12];
    float* out = (float*)d_out;

    void *pA0, *phx, *pux, *ph, *pwin, *pw1, *pw2, *pwz, *pwm;
    cudaGetSymbolAddress(&pA0, g_A0);
    cudaGetSymbolAddress(&phx, g_hx);
    cudaGetSymbolAddress(&pux, g_ux);
    cudaGetSymbolAddress(&ph, g_h);
    cudaGetSymbolAddress(&pwin, g_wq_in);
    cudaGetSymbolAddress(&pw1, g_wq1);
    cudaGetSymbolAddress(&pw2, g_wq2);
    cudaGetSymbolAddress(&pwz, g_wqz);
    cudaGetSymbolAddress(&pwm, g_wqm);

    __half* wq_in = (__half*)pwin;
    __half* wq1   = (__half*)pw1;
    __half* wq2   = (__half*)pw2;

    cudaFuncSetAttribute(k_fused, cudaFuncAttributeMaxDynamicSharedMemorySize, SMEM_DYN);

    P7 pa;
    pa.w[0] = W_in;                      pa.n[0] = (long)DIMX * KIN;
    pa.w[1] = W1;                        pa.n[1] = (long)HIDX * DIMX;
    pa.w[2] = W1 + (size_t)HIDX * DIMX;  pa.n[2] = (long)HIDX * DIMX;
    pa.w[3] = W2;                        pa.n[3] = (long)DIMX * HIDX;
    pa.w[4] = W2 + (size_t)DIMX * HIDX;  pa.n[4] = (long)DIMX * HIDX;
    pa.w[5] = W_z;                       pa.n[5] = (long)DIMX * DIMX;
    pa.w[6] = W_m;                       pa.n[6] = (long)DIMX;
    k_absbuild<<<dim3(NPART, 8), 256>>>(pa, (const float4*)x, (const float4*)y,
                                        (const float4*)sp);
    k_finalize<<<1, 1024>>>();

    Q7 qa;
    for (int i = 0; i < 7; i++) { qa.w[i] = pa.w[i]; qa.n[i] = pa.n[i]; }
    qa.q[0] = wq_in;
    qa.q[1] = wq1;
    qa.q[2] = wq1 + (size_t)HIDX * DIMX;
    qa.q[3] = wq2;
    qa.q[4] = wq2 + (size_t)DIMX * HIDX;
    qa.q[5] = (__half*)pwz;
    qa.q[6] = (__half*)pwm;
    k_quant7<<<dim3(2048, 7), 256>>>(qa);

    Params P;
    // s0: h = A0 @ Win^T + b_in
    P.gp[0] = { (__half*)pA0, wq_in, b_in, (float*)ph, (__half*)phx, nullptr,
                KIN, DIMX, 8, TM * 8, 0, EPI_H, 0 };
    // s1: u = gelu(h @ W1_0^T + b1_0)
    P.gp[1] = { (__half*)phx, wq1, b1, nullptr, (__half*)pux, nullptr,
                DIMX, HIDX, 32, TM * 32, 1, EPI_GELU, 8 };
    // s2: h += u @ W2_0^T + b2_0
    P.gp[2] = { (__half*)pux, wq2, b2, (float*)ph, (__half*)phx, nullptr,
                HIDX, DIMX, 8, TM * 8, 3, EPI_RES, 32 };
    // s3: u = gelu(h @ W1_1^T + b1_1)
    P.gp[3] = { (__half*)phx, wq1 + (size_t)HIDX * DIMX, b1 + HIDX, nullptr,
                (__half*)pux, nullptr, DIMX, HIDX, 32, TM * 32, 2, EPI_GELU, 8 };
    // s4: h += u @ W2_1^T + b2_1
    P.gp[4] = { (__half*)pux, wq2 + (size_t)DIMX * HIDX, b2 + DIMX, (float*)ph,
                (__half*)phx, nullptr, HIDX, DIMX, 8, TM * 8, 4, EPI_RES, 32 };
    // s5: z = h @ Wz^T + b_z  (straight to d_out)
    P.gp[5] = { (__half*)phx, (__half*)pwz, b_z, nullptr, nullptr, out,
                DIMX, DIMX, 8, TM * 8, 5, EPI_Z, 8 };
    P.bm = b_m;
    P.outF = out + (size_t)NROWS * DIMX;

    k_fused<<<NPCTA, 256, SMEM_DYN>>>(P);   // launch 4: ncu-captured
}